// round 1
// baseline (speedup 1.0000x reference)
#include <cuda_runtime.h>
#include <math.h>

#define N_NODES 20000
#define N_EDGES 50000
#define C 64
#define NREL 32
#define ORDER_CAP 52032      // >= N_EDGES + NREL*63 = 52016, multiple of 64
#define TILE_CAP 832         // >= ORDER_CAP/64 = 813

// ---------------- scratch (no allocations allowed) ----------------
__device__ int   g_cnt_src[N_NODES];
__device__ int   g_cnt_dst[N_NODES];
__device__ float g_inv[2][NREL];
__device__ int   g_hist[NREL];
__device__ int   g_cursor[NREL];
__device__ int   g_poff[NREL + 1];
__device__ int   g_ntiles;
__device__ int   g_tile_rel[TILE_CAP];
__device__ int   g_order[ORDER_CAP];
__device__ int   g_is64;

// index load that works for int64 or int32 buffers
__device__ __forceinline__ int load_idx(const void* p, int i, int is64) {
    if (is64) return (int)((const long long*)p)[i];
    return ((const int*)p)[i];
}

// ---------------- init / reset (every replay) ----------------
__global__ void k_zero() {
    int i = blockIdx.x * blockDim.x + threadIdx.x;
    if (i < N_NODES) { g_cnt_src[i] = 0; g_cnt_dst[i] = 0; }
    if (i < ORDER_CAP) g_order[i] = -1;
    if (i < NREL) { g_hist[i] = 0; g_cursor[i] = 0; }
    if (i == 0) g_is64 = 1;
}

// detect index element width: int64-interpretation of int32 data explodes range
__global__ void k_detect(const void* ei) {
    int i = blockIdx.x * blockDim.x + threadIdx.x;   // 2048 probes, safe for both widths
    long long v = ((const long long*)ei)[i];
    if (v < 0 || v >= (long long)N_NODES) g_is64 = 0;
}

// per-relation 1/(||W_r||+0.01) for both tables
__global__ void k_norm(const float* __restrict__ wf, const float* __restrict__ wb) {
    __shared__ float red[256];
    int r = blockIdx.x & (NREL - 1);
    int tab = blockIdx.x >> 5;
    const float* w = (tab ? wb : wf) + r * (C * C);
    float s = 0.f;
    for (int j = threadIdx.x; j < C * C; j += 256) { float v = w[j]; s += v * v; }
    red[threadIdx.x] = s; __syncthreads();
    for (int off = 128; off > 0; off >>= 1) {
        if (threadIdx.x < off) red[threadIdx.x] += red[threadIdx.x + off];
        __syncthreads();
    }
    if (threadIdx.x == 0) g_inv[tab][r] = 1.f / (sqrtf(red[0]) + 0.01f);
}

__global__ void k_count(const void* __restrict__ ei, const void* __restrict__ et) {
    int e = blockIdx.x * blockDim.x + threadIdx.x;
    if (e >= N_EDGES) return;
    int is64 = g_is64;
    atomicAdd(&g_cnt_src[load_idx(ei, e, is64)], 1);
    atomicAdd(&g_cnt_dst[load_idx(ei, N_EDGES + e, is64)], 1);
    atomicAdd(&g_hist[load_idx(et, e, is64)], 1);
}

__global__ void k_scan() {
    if (threadIdx.x != 0) return;
    int run = 0;
    for (int r = 0; r < NREL; r++) {
        g_poff[r] = run;
        int nt = (g_hist[r] + 63) >> 6;
        int t0 = run >> 6;
        for (int t = 0; t < nt; t++) g_tile_rel[t0 + t] = r;
        run += nt << 6;
    }
    g_poff[NREL] = run;
    g_ntiles = run >> 6;
}

__global__ void k_scatter(const void* __restrict__ et) {
    int e = blockIdx.x * blockDim.x + threadIdx.x;
    if (e >= N_EDGES) return;
    int r = load_idx(et, e, g_is64);
    int pos = g_poff[r] + atomicAdd(&g_cursor[r], 1);
    g_order[pos] = e;
}

// ---------------- linear term: out = x @ lin_w^T + b  (initializes out) ------
__global__ __launch_bounds__(256) void k_linear(
    const float* __restrict__ x, const float* __restrict__ lw,
    const float* __restrict__ lb, float* __restrict__ out)
{
    __shared__ __align__(16) float Xs[64 * 68];
    __shared__ __align__(16) float Ws[64 * 68];
    int tid = threadIdx.x;
    int node0 = blockIdx.x * 64;

    int m = tid >> 2, kq = (tid & 3) << 4;
    int node = node0 + m;
    if (node < N_NODES) {
        const float4* xr = (const float4*)(x + (size_t)node * C + kq);
        #pragma unroll
        for (int t = 0; t < 4; t++) *(float4*)&Xs[m * 68 + kq + 4 * t] = xr[t];
    } else {
        float4 z = make_float4(0.f, 0.f, 0.f, 0.f);
        #pragma unroll
        for (int t = 0; t < 4; t++) *(float4*)&Xs[m * 68 + kq + 4 * t] = z;
    }
    // Ws[k][n] = lin_w[n][k]
    for (int idx = tid; idx < C * C; idx += 256) {
        int n = idx >> 6, k = idx & 63;
        Ws[k * 68 + n] = lw[idx];
    }
    __syncthreads();

    int tx = tid & 15, ty = tid >> 4;
    float acc[4][4] = {};
    #pragma unroll 16
    for (int k = 0; k < C; k++) {
        float4 b = *(const float4*)&Ws[k * 68 + tx * 4];
        #pragma unroll
        for (int i = 0; i < 4; i++) {
            float a = Xs[(ty * 4 + i) * 68 + k];
            acc[i][0] += a * b.x; acc[i][1] += a * b.y;
            acc[i][2] += a * b.z; acc[i][3] += a * b.w;
        }
    }
    float4 bias = *(const float4*)(lb + tx * 4);
    #pragma unroll
    for (int i = 0; i < 4; i++) {
        int n = node0 + ty * 4 + i;
        if (n < N_NODES) {
            float4 o = make_float4(acc[i][0] + bias.x, acc[i][1] + bias.y,
                                   acc[i][2] + bias.z, acc[i][3] + bias.w);
            *(float4*)(out + (size_t)n * C + tx * 4) = o;
        }
    }
}

// ---------------- conv: 64-edge x 64-out tile GEMM + atomic scatter ----------
__global__ __launch_bounds__(256) void k_conv(
    const float* __restrict__ x, const void* __restrict__ ei,
    const float* __restrict__ wf, const float* __restrict__ wb,
    float* __restrict__ out)
{
    __shared__ __align__(16) float As[64 * 68];
    __shared__ __align__(16) float Bs[64 * 64];
    __shared__ int   Ss[64];
    __shared__ int   Ds[64];
    __shared__ float Cs[64];

    int tile = blockIdx.x;
    if (tile >= g_ntiles) return;
    int dir = blockIdx.y;
    int r = g_tile_rel[tile];
    int tid = threadIdx.x;
    int is64 = g_is64;

    if (tid < 64) {
        int eid = g_order[tile * 64 + tid];
        int s = 0, d = -1; float c = 0.f;
        if (eid >= 0) {
            if (dir == 0) {
                s = load_idx(ei, eid, is64);
                d = load_idx(ei, N_EDGES + eid, is64);
                c = g_inv[0][r] / (float)(g_cnt_src[s] + 1);
            } else {
                s = load_idx(ei, N_EDGES + eid, is64);
                d = load_idx(ei, eid, is64);
                c = g_inv[1][r] / (float)(g_cnt_dst[s] + 1);
            }
        }
        Ss[tid] = s; Ds[tid] = d; Cs[tid] = c;
    }
    // W_r -> smem (row-major [k][n] matches gmem layout)
    {
        const float4* w4 = (const float4*)((dir ? wb : wf) + (size_t)r * C * C);
        #pragma unroll
        for (int t = 0; t < 4; t++)
            *(float4*)&Bs[(tid + 256 * t) * 4] = w4[tid + 256 * t];
    }
    __syncthreads();

    // gather x rows, scale by coef, into As[m][k] (pad 68)
    {
        int m = tid >> 2, kq = (tid & 3) << 4;
        float cm = Cs[m];
        const float4* xr = (const float4*)(x + (size_t)Ss[m] * C + kq);
        #pragma unroll
        for (int t = 0; t < 4; t++) {
            float4 v = xr[t];
            v.x *= cm; v.y *= cm; v.z *= cm; v.w *= cm;
            *(float4*)&As[m * 68 + kq + 4 * t] = v;
        }
    }
    __syncthreads();

    int tx = tid & 15, ty = tid >> 4;
    float acc[4][4] = {};
    #pragma unroll 16
    for (int k = 0; k < C; k++) {
        float4 b = *(const float4*)&Bs[k * 64 + tx * 4];
        #pragma unroll
        for (int i = 0; i < 4; i++) {
            float a = As[(ty * 4 + i) * 68 + k];
            acc[i][0] += a * b.x; acc[i][1] += a * b.y;
            acc[i][2] += a * b.z; acc[i][3] += a * b.w;
        }
    }

    #pragma unroll
    for (int i = 0; i < 4; i++) {
        int d = Ds[ty * 4 + i];
        if (d >= 0) {
            float* o = out + (size_t)d * C + tx * 4;
            atomicAdd(o + 0, acc[i][0]);
            atomicAdd(o + 1, acc[i][1]);
            atomicAdd(o + 2, acc[i][2]);
            atomicAdd(o + 3, acc[i][3]);
        }
    }
}

// ---------------- launch ----------------
extern "C" void kernel_launch(void* const* d_in, const int* in_sizes, int n_in,
                              void* d_out, int out_size)
{
    const float* x  = (const float*)d_in[0];
    const void*  ei = d_in[1];
    const void*  et = d_in[2];
    const float* wf = (const float*)d_in[3];
    const float* wb = (const float*)d_in[4];
    const float* lw = (const float*)d_in[5];
    const float* lb = (const float*)d_in[6];
    float* out = (float*)d_out;

    k_zero<<<(ORDER_CAP + 255) / 256, 256>>>();
    k_detect<<<8, 256>>>(ei);
    k_norm<<<64, 256>>>(wf, wb);
    k_count<<<(N_EDGES + 255) / 256, 256>>>(ei, et);
    k_scan<<<1, 32>>>();
    k_scatter<<<(N_EDGES + 255) / 256, 256>>>(et);
    k_linear<<<(N_NODES + 63) / 64, 256>>>(x, lw, lb, out);
    dim3 g(816, 2);
    k_conv<<<g, 256>>>(x, ei, wf, wb, out);
}

// round 2
// speedup vs baseline: 1.4596x; 1.4596x over previous
#include <cuda_runtime.h>
#include <math.h>

#define N_NODES 20000
#define N_EDGES 50000
#define C 64
#define NREL 32
#define MAXTILES 424                 // >= sum ceil(h_r/128) worst case (422)
#define ORDER_CAP (MAXTILES * 128)   // 54272

// ---------------- scratch (no allocations allowed) ----------------
struct __align__(16) GScratch {
    int cnt_src[N_NODES];
    int cnt_dst[N_NODES];
    int hist[NREL];
    int cursor[NREL];
    int order[ORDER_CAP];            // stores e+1; 0 = empty/pad
};
__device__ GScratch G;
__device__ float g_inv[2][NREL];
__device__ int g_is64;

__device__ __forceinline__ int load_idx(const void* p, int i, int is64) {
    return is64 ? (int)((const long long*)p)[i] : ((const int*)p)[i];
}

// ---------------- prep: zero scratch + detect width + per-rel norms ----------
__global__ __launch_bounds__(256) void k_prep(
    const float* __restrict__ wf, const float* __restrict__ wb,
    const void* __restrict__ ei)
{
    int b = blockIdx.x, tid = threadIdx.x;
    if (b < 64) {
        // 1/(||W_r||+0.01) for both tables
        __shared__ float red[256];
        int r = b & 31, tab = b >> 5;
        const float* w = (tab ? wb : wf) + (size_t)r * (C * C);
        float s = 0.f;
        for (int j = tid; j < C * C; j += 256) { float v = w[j]; s += v * v; }
        red[tid] = s; __syncthreads();
        for (int o = 128; o > 0; o >>= 1) {
            if (tid < o) red[tid] += red[tid + o];
            __syncthreads();
        }
        if (tid == 0) g_inv[tab][r] = 1.f / (sqrtf(red[0]) + 0.01f);
    } else if (b == 64) {
        // width detect: if int64, high words of first 32 entries are all 0
        if (tid < 32) {
            int hi = ((const int*)ei)[2 * tid + 1];
            unsigned ok = __ballot_sync(0xFFFFFFFFu, hi == 0);
            if (tid == 0) g_is64 = (ok == 0xFFFFFFFFu) ? 1 : 0;
        }
    } else {
        int i = (b - 65) * 256 + tid;
        const int n16 = (int)(sizeof(GScratch) / 16);
        if (i < n16) ((int4*)&G)[i] = make_int4(0, 0, 0, 0);
    }
}

// ---------------- count: degrees + relation histogram (smem-aggregated) -----
__global__ __launch_bounds__(256) void k_count(
    const void* __restrict__ ei, const void* __restrict__ et)
{
    __shared__ int h[NREL];
    int tid = threadIdx.x;
    if (tid < NREL) h[tid] = 0;
    __syncthreads();
    int e = blockIdx.x * 256 + tid;
    int is64 = g_is64;
    if (e < N_EDGES) {
        atomicAdd(&G.cnt_src[load_idx(ei, e, is64)], 1);
        atomicAdd(&G.cnt_dst[load_idx(ei, N_EDGES + e, is64)], 1);
        atomicAdd(&h[load_idx(et, e, is64)], 1);
    }
    __syncthreads();
    if (tid < NREL && h[tid]) atomicAdd(&G.hist[tid], h[tid]);
}

// ---------------- scatter (sorted-by-rel order) + linear GEMM, one launch ---
#define SCAT_BLOCKS 196
__global__ __launch_bounds__(256) void k_scatlin(
    const void* __restrict__ et, const float* __restrict__ x,
    const float* __restrict__ lw, const float* __restrict__ lb,
    float* __restrict__ out)
{
    int tid = threadIdx.x;
    if (blockIdx.x < SCAT_BLOCKS) {
        __shared__ int obase[NREL];
        __shared__ int bcnt[NREL];
        __shared__ int gbase[NREL];
        if (tid < 32) {
            int nt = (G.hist[tid] + 127) >> 7;
            int a = nt;
            #pragma unroll
            for (int o = 1; o < 32; o <<= 1) {
                int v = __shfl_up_sync(0xFFFFFFFFu, a, o);
                if (tid >= o) a += v;
            }
            obase[tid] = (a - nt) * 128;   // 128-aligned slot base per relation
            bcnt[tid] = 0;
        }
        __syncthreads();
        int e = blockIdx.x * 256 + tid;
        int r = 0, my = 0, valid = (e < N_EDGES);
        if (valid) {
            r = load_idx(et, e, g_is64);
            my = atomicAdd(&bcnt[r], 1);
        }
        __syncthreads();
        if (tid < 32 && bcnt[tid]) gbase[tid] = atomicAdd(&G.cursor[tid], bcnt[tid]);
        __syncthreads();
        if (valid) G.order[obase[r] + gbase[r] + my] = e + 1;
    } else {
        // linear term: out = x @ lin_w^T + b (initializes out)
        __shared__ __align__(16) float Xs[64 * 68];
        __shared__ __align__(16) float Ws[64 * 68];
        int node0 = (blockIdx.x - SCAT_BLOCKS) * 64;

        int m = tid >> 2, kq = (tid & 3) << 4;
        int node = node0 + m;
        if (node < N_NODES) {
            const float4* xr = (const float4*)(x + (size_t)node * C + kq);
            #pragma unroll
            for (int t = 0; t < 4; t++) *(float4*)&Xs[m * 68 + kq + 4 * t] = xr[t];
        } else {
            float4 z = make_float4(0.f, 0.f, 0.f, 0.f);
            #pragma unroll
            for (int t = 0; t < 4; t++) *(float4*)&Xs[m * 68 + kq + 4 * t] = z;
        }
        for (int idx = tid; idx < C * C; idx += 256) {
            int n = idx >> 6, k = idx & 63;
            Ws[k * 68 + n] = lw[idx];
        }
        __syncthreads();

        int tx = tid & 15, ty = tid >> 4;
        float acc[4][4] = {};
        #pragma unroll 16
        for (int k = 0; k < C; k++) {
            float4 b = *(const float4*)&Ws[k * 68 + tx * 4];
            #pragma unroll
            for (int i = 0; i < 4; i++) {
                float a = Xs[(ty * 4 + i) * 68 + k];
                acc[i][0] += a * b.x; acc[i][1] += a * b.y;
                acc[i][2] += a * b.z; acc[i][3] += a * b.w;
            }
        }
        float4 bias = *(const float4*)(lb + tx * 4);
        #pragma unroll
        for (int i = 0; i < 4; i++) {
            int n = node0 + ty * 4 + i;
            if (n < N_NODES) {
                *(float4*)(out + (size_t)n * C + tx * 4) =
                    make_float4(acc[i][0] + bias.x, acc[i][1] + bias.y,
                                acc[i][2] + bias.z, acc[i][3] + bias.w);
            }
        }
    }
}

// ---------------- conv: 128-edge x 64-out tile GEMM + atomic scatter --------
// dynamic smem layout (floats):
//   As[64*128]  (A^T: [k][m])   8192
//   Bs[64*64]   (W_r: [k][n])   4096
//   Ss[128] Ds[128] Cs[128] Tst[33]
#define CONV_SMEM_FLOATS (8192 + 4096 + 128 * 3 + 33)
#define CONV_SMEM_BYTES (CONV_SMEM_FLOATS * 4)

__global__ __launch_bounds__(256) void k_conv(
    const float* __restrict__ x, const void* __restrict__ ei,
    const float* __restrict__ wf, const float* __restrict__ wb,
    float* __restrict__ out)
{
    extern __shared__ float sm[];
    float* As = sm;
    float* Bs = sm + 8192;
    int*   Ss = (int*)(Bs + 4096);
    int*   Ds = Ss + 128;
    float* Cs = (float*)(Ds + 128);
    int*   Tst = (int*)(Cs + 128);

    int tid = threadIdx.x;
    int dir = blockIdx.y;
    int tile = blockIdx.x;

    // per-block tile-start scan over relations (cheap: one warp, ~100 cyc)
    if (tid < 32) {
        int nt = (G.hist[tid] + 127) >> 7;
        int a = nt;
        #pragma unroll
        for (int o = 1; o < 32; o <<= 1) {
            int v = __shfl_up_sync(0xFFFFFFFFu, a, o);
            if (tid >= o) a += v;
        }
        Tst[tid] = a - nt;
        if (tid == 31) Tst[32] = a;
    }
    __syncthreads();
    if (tile >= Tst[32]) return;

    int r = 0;
    while (r < 31 && Tst[r + 1] <= tile) r++;
    float inv = g_inv[dir][r];
    int is64 = g_is64;

    // edge metadata for the 128 rows of this tile
    if (tid < 128) {
        int ep = G.order[tile * 128 + tid];
        int s = 0, d = -1; float c = 0.f;
        if (ep > 0) {
            int e = ep - 1;
            int a = load_idx(ei, e, is64);             // src
            int b2 = load_idx(ei, N_EDGES + e, is64);  // dst
            if (dir) { int t = a; a = b2; b2 = t; }    // reversed conv
            s = a; d = b2;
            int cnt = dir ? G.cnt_dst[s] : G.cnt_src[s];
            c = inv / (float)(cnt + 1);
        }
        Ss[tid] = s; Ds[tid] = d; Cs[tid] = c;
    }
    // W_r -> smem ([k][n], matches gmem layout)
    {
        const float4* w4 = (const float4*)((dir ? wb : wf) + (size_t)r * (C * C));
        float4* b4 = (float4*)Bs;
        #pragma unroll
        for (int t = 0; t < 4; t++) b4[tid + 256 * t] = w4[tid + 256 * t];
    }
    __syncthreads();

    // gather: As[k][m] = x[s_m][k] * c_m   (STS conflict-free: m consecutive)
    {
        int m = tid & 127, kg = tid >> 7;      // kg: k-half 0/1
        float c = Cs[m];
        const float4* xr = (const float4*)(x + (size_t)Ss[m] * C + kg * 32);
        #pragma unroll
        for (int j = 0; j < 8; j++) {
            float4 v = xr[j];
            int kb = kg * 32 + j * 4;
            As[(kb + 0) * 128 + m] = v.x * c;
            As[(kb + 1) * 128 + m] = v.y * c;
            As[(kb + 2) * 128 + m] = v.z * c;
            As[(kb + 3) * 128 + m] = v.w * c;
        }
    }
    __syncthreads();

    // 128x64x64 GEMM: thread (tx,ty) owns rows ty*8..+7, cols tx*4..+3
    int tx = tid & 15, ty = tid >> 4;
    float acc[8][4] = {};
    #pragma unroll 8
    for (int k = 0; k < C; k++) {
        float4 bv = *(const float4*)&Bs[k * 64 + tx * 4];
        float4 a0 = *(const float4*)&As[k * 128 + ty * 8];
        float4 a1 = *(const float4*)&As[k * 128 + ty * 8 + 4];
        acc[0][0] += a0.x * bv.x; acc[0][1] += a0.x * bv.y; acc[0][2] += a0.x * bv.z; acc[0][3] += a0.x * bv.w;
        acc[1][0] += a0.y * bv.x; acc[1][1] += a0.y * bv.y; acc[1][2] += a0.y * bv.z; acc[1][3] += a0.y * bv.w;
        acc[2][0] += a0.z * bv.x; acc[2][1] += a0.z * bv.y; acc[2][2] += a0.z * bv.z; acc[2][3] += a0.z * bv.w;
        acc[3][0] += a0.w * bv.x; acc[3][1] += a0.w * bv.y; acc[3][2] += a0.w * bv.z; acc[3][3] += a0.w * bv.w;
        acc[4][0] += a1.x * bv.x; acc[4][1] += a1.x * bv.y; acc[4][2] += a1.x * bv.z; acc[4][3] += a1.x * bv.w;
        acc[5][0] += a1.y * bv.x; acc[5][1] += a1.y * bv.y; acc[5][2] += a1.y * bv.z; acc[5][3] += a1.y * bv.w;
        acc[6][0] += a1.z * bv.x; acc[6][1] += a1.z * bv.y; acc[6][2] += a1.z * bv.z; acc[6][3] += a1.z * bv.w;
        acc[7][0] += a1.w * bv.x; acc[7][1] += a1.w * bv.y; acc[7][2] += a1.w * bv.z; acc[7][3] += a1.w * bv.w;
    }

    #pragma unroll
    for (int i = 0; i < 8; i++) {
        int d = Ds[ty * 8 + i];
        if (d >= 0) {
            float* o = out + (size_t)d * C + tx * 4;
            atomicAdd(o + 0, acc[i][0]);
            atomicAdd(o + 1, acc[i][1]);
            atomicAdd(o + 2, acc[i][2]);
            atomicAdd(o + 3, acc[i][3]);
        }
    }
}

// ---------------- launch ----------------
extern "C" void kernel_launch(void* const* d_in, const int* in_sizes, int n_in,
                              void* d_out, int out_size)
{
    const float* x  = (const float*)d_in[0];
    const void*  ei = d_in[1];
    const void*  et = d_in[2];
    const float* wf = (const float*)d_in[3];
    const float* wb = (const float*)d_in[4];
    const float* lw = (const float*)d_in[5];
    const float* lb = (const float*)d_in[6];
    float* out = (float*)d_out;

    cudaFuncSetAttribute(k_conv, cudaFuncAttributeMaxDynamicSharedMemorySize,
                         CONV_SMEM_BYTES);

    const int zero_blocks = (int)((sizeof(GScratch) / 16 + 255) / 256); // 93
    k_prep<<<64 + 1 + zero_blocks, 256>>>(wf, wb, ei);
    k_count<<<(N_EDGES + 255) / 256, 256>>>(ei, et);
    k_scatlin<<<SCAT_BLOCKS + (N_NODES + 63) / 64, 256>>>(et, x, lw, lb, out);
    dim3 g(MAXTILES, 2);
    k_conv<<<g, 256, CONV_SMEM_BYTES>>>(x, ei, wf, wb, out);
}

// round 3
// speedup vs baseline: 1.5063x; 1.0320x over previous
#include <cuda_runtime.h>
#include <math.h>

#define N_NODES 20000
#define N_EDGES 50000
#define C 64
#define NREL 32
#define MAXTILES 424                 // >= 50000/128 + 32
#define ORDER_CAP (MAXTILES * 128)   // 54272

// ---------------- scratch (no allocations allowed) ----------------
struct __align__(16) GScratch {
    int cnt_src[N_NODES];
    int cnt_dst[N_NODES];
    int hist[NREL];
    int cursor[NREL];
    int order[ORDER_CAP];            // stores e+1; 0 = empty/pad
};
__device__ GScratch G;
__device__ float g_inv[2][NREL];
__device__ int g_is64;

__device__ __forceinline__ int load_idx(const void* p, int i, int is64) {
    return is64 ? (int)((const long long*)p)[i] : ((const int*)p)[i];
}
__device__ __forceinline__ unsigned f2tf(float f) {
    unsigned u; asm("cvt.rna.tf32.f32 %0, %1;" : "=r"(u) : "f"(f)); return u;
}
// v -> (hi, lo) both already tf32-rounded, stored as float bit patterns
__device__ __forceinline__ void split_tf(float v, float& hi, float& lo) {
    float h = __uint_as_float(f2tf(v));
    hi = h;
    lo = __uint_as_float(f2tf(v - h));
}
__device__ __forceinline__ void mma_tf32(float* d,
    unsigned a0, unsigned a1, unsigned a2, unsigned a3,
    unsigned b0, unsigned b1)
{
    asm volatile(
        "mma.sync.aligned.m16n8k8.row.col.f32.tf32.tf32.f32 "
        "{%0,%1,%2,%3},{%4,%5,%6,%7},{%8,%9},{%0,%1,%2,%3};"
        : "+f"(d[0]), "+f"(d[1]), "+f"(d[2]), "+f"(d[3])
        : "r"(a0), "r"(a1), "r"(a2), "r"(a3), "r"(b0), "r"(b1));
}
__device__ __forceinline__ void red2(float* p, float a, float b) {
    asm volatile("red.global.add.v2.f32 [%0], {%1, %2};"
                 :: "l"(p), "f"(a), "f"(b) : "memory");
}
// swizzled index for [rows][64] arrays: element (m,k)
#define SWZ(m, k) ((m) * 64 + ((((k) >> 2) ^ ((m) & 7)) << 2) + ((k) & 3))

// ---------------- prep: zero scratch + detect width + per-rel norms ----------
__global__ __launch_bounds__(256) void k_prep(
    const float* __restrict__ wf, const float* __restrict__ wb,
    const void* __restrict__ ei)
{
    int b = blockIdx.x, tid = threadIdx.x;
    if (b < 64) {
        __shared__ float red[256];
        int r = b & 31, tab = b >> 5;
        const float* w = (tab ? wb : wf) + (size_t)r * (C * C);
        float s = 0.f;
        for (int j = tid; j < C * C; j += 256) { float v = w[j]; s += v * v; }
        red[tid] = s; __syncthreads();
        for (int o = 128; o > 0; o >>= 1) {
            if (tid < o) red[tid] += red[tid + o];
            __syncthreads();
        }
        if (tid == 0) g_inv[tab][r] = 1.f / (sqrtf(red[0]) + 0.01f);
    } else if (b == 64) {
        if (tid < 32) {
            int hi = ((const int*)ei)[2 * tid + 1];
            unsigned ok = __ballot_sync(0xFFFFFFFFu, hi == 0);
            if (tid == 0) g_is64 = (ok == 0xFFFFFFFFu) ? 1 : 0;
        }
    } else {
        int i = (b - 65) * 256 + tid;
        const int n16 = (int)(sizeof(GScratch) / 16);
        if (i < n16) ((int4*)&G)[i] = make_int4(0, 0, 0, 0);
    }
}

// ---------------- count: degrees + relation histogram -----------------------
__global__ __launch_bounds__(256) void k_count(
    const void* __restrict__ ei, const void* __restrict__ et)
{
    __shared__ int h[NREL];
    int tid = threadIdx.x;
    if (tid < NREL) h[tid] = 0;
    __syncthreads();
    int e = blockIdx.x * 256 + tid;
    int is64 = g_is64;
    if (e < N_EDGES) {
        atomicAdd(&G.cnt_src[load_idx(ei, e, is64)], 1);
        atomicAdd(&G.cnt_dst[load_idx(ei, N_EDGES + e, is64)], 1);
        atomicAdd(&h[load_idx(et, e, is64)], 1);
    }
    __syncthreads();
    if (tid < NREL && h[tid]) atomicAdd(&G.hist[tid], h[tid]);
}

// ---------------- scatter (sort-by-rel) + linear term (tensor-core) ---------
#define SCAT_BLOCKS 196
#define LIN_BLOCKS ((N_NODES + 127) / 128)
#define TC_SMEM_FLOATS (8192 + 8192 + 4096 + 4096)
#define SCAT_SMEM_BYTES (TC_SMEM_FLOATS * 4)

__global__ __launch_bounds__(256, 2) void k_scatlin(
    const void* __restrict__ et, const float* __restrict__ x,
    const float* __restrict__ lw, const float* __restrict__ lb,
    float* __restrict__ out)
{
    int tid = threadIdx.x;
    if (blockIdx.x < SCAT_BLOCKS) {
        __shared__ int obase[NREL];
        __shared__ int bcnt[NREL];
        __shared__ int gbase[NREL];
        if (tid < 32) {
            int nt = (G.hist[tid] + 127) >> 7;
            int a = nt;
            #pragma unroll
            for (int o = 1; o < 32; o <<= 1) {
                int v = __shfl_up_sync(0xFFFFFFFFu, a, o);
                if (tid >= o) a += v;
            }
            obase[tid] = (a - nt) * 128;
            bcnt[tid] = 0;
        }
        __syncthreads();
        int e = blockIdx.x * 256 + tid;
        int r = 0, my = 0, valid = (e < N_EDGES);
        if (valid) {
            r = load_idx(et, e, g_is64);
            my = atomicAdd(&bcnt[r], 1);
        }
        __syncthreads();
        if (tid < 32 && bcnt[tid]) gbase[tid] = atomicAdd(&G.cursor[tid], bcnt[tid]);
        __syncthreads();
        if (valid) G.order[obase[r] + gbase[r] + my] = e + 1;
        return;
    }

    // ---- linear: out = x @ lw^T + b, 128-node tiles, 3xTF32 mma ----
    extern __shared__ float sm[];
    float* Ah  = sm;
    float* Al  = sm + 8192;
    float* Bth = sm + 16384;
    float* Btl = sm + 20480;

    int node0 = (blockIdx.x - SCAT_BLOCKS) * 128;

    // B = lw (row n, col k) -> Bt[n][k] swizzled, split hi/lo
    {
        const float4* w4 = (const float4*)lw;
        #pragma unroll
        for (int q = 0; q < 4; q++) {
            int i4 = tid + 256 * q;
            float4 v = w4[i4];                 // row n = i4>>4, cols k4..k4+3
            int n = i4 >> 4;
            int k4 = (i4 & 15);                // float4 group index
            int pg = k4 ^ (n & 7);
            float4 hi, lo;
            split_tf(v.x, hi.x, lo.x); split_tf(v.y, hi.y, lo.y);
            split_tf(v.z, hi.z, lo.z); split_tf(v.w, hi.w, lo.w);
            *(float4*)&Bth[n * 64 + pg * 4] = hi;
            *(float4*)&Btl[n * 64 + pg * 4] = lo;
        }
    }
    // A = x rows (clamped), split hi/lo
    {
        int m = tid & 127, h = tid >> 7;
        int node = node0 + m;
        if (node >= N_NODES) node = 0;
        const float4* xr = (const float4*)(x + (size_t)node * C + h * 32);
        #pragma unroll
        for (int q = 0; q < 8; q++) {
            float4 v = xr[q];
            int kg = h * 8 + q;
            int pg = kg ^ (m & 7);
            float4 hi, lo;
            split_tf(v.x, hi.x, lo.x); split_tf(v.y, hi.y, lo.y);
            split_tf(v.z, hi.z, lo.z); split_tf(v.w, hi.w, lo.w);
            *(float4*)&Ah[m * 64 + pg * 4] = hi;
            *(float4*)&Al[m * 64 + pg * 4] = lo;
        }
    }
    __syncthreads();

    int lane = tid & 31, w = tid >> 5;
    int gid = lane >> 2, tig = lane & 3;
    int m0 = w * 16;
    float d[8][4] = {};
    #pragma unroll
    for (int s8 = 0; s8 < 8; s8++) {
        int kg = 2 * s8;
        int mA = m0 + gid, xa = mA & 7;
        unsigned ah0 = __float_as_uint(Ah[mA * 64 + ((kg ^ xa) << 2) + tig]);
        unsigned ah1 = __float_as_uint(Ah[(mA + 8) * 64 + ((kg ^ xa) << 2) + tig]);
        unsigned ah2 = __float_as_uint(Ah[mA * 64 + (((kg + 1) ^ xa) << 2) + tig]);
        unsigned ah3 = __float_as_uint(Ah[(mA + 8) * 64 + (((kg + 1) ^ xa) << 2) + tig]);
        unsigned al0 = __float_as_uint(Al[mA * 64 + ((kg ^ xa) << 2) + tig]);
        unsigned al1 = __float_as_uint(Al[(mA + 8) * 64 + ((kg ^ xa) << 2) + tig]);
        unsigned al2 = __float_as_uint(Al[mA * 64 + (((kg + 1) ^ xa) << 2) + tig]);
        unsigned al3 = __float_as_uint(Al[(mA + 8) * 64 + (((kg + 1) ^ xa) << 2) + tig]);
        #pragma unroll
        for (int j = 0; j < 8; j++) {
            int nB = j * 8 + gid;              // nB & 7 == gid
            unsigned bh0 = __float_as_uint(Bth[nB * 64 + ((kg ^ gid) << 2) + tig]);
            unsigned bh1 = __float_as_uint(Bth[nB * 64 + (((kg + 1) ^ gid) << 2) + tig]);
            unsigned bl0 = __float_as_uint(Btl[nB * 64 + ((kg ^ gid) << 2) + tig]);
            unsigned bl1 = __float_as_uint(Btl[nB * 64 + (((kg + 1) ^ gid) << 2) + tig]);
            mma_tf32(d[j], ah0, ah1, ah2, ah3, bh0, bh1);
            mma_tf32(d[j], al0, al1, al2, al3, bh0, bh1);
            mma_tf32(d[j], ah0, ah1, ah2, ah3, bl0, bl1);
        }
    }
    // epilogue: + bias, plain stores
    int r0 = m0 + gid, r1 = r0 + 8;
    #pragma unroll
    for (int j = 0; j < 8; j++) {
        int n = j * 8 + 2 * tig;
        float2 bias = *(const float2*)(lb + n);
        if (node0 + r0 < N_NODES) {
            *(float2*)(out + (size_t)(node0 + r0) * C + n) =
                make_float2(d[j][0] + bias.x, d[j][1] + bias.y);
        }
        if (node0 + r1 < N_NODES) {
            *(float2*)(out + (size_t)(node0 + r1) * C + n) =
                make_float2(d[j][2] + bias.x, d[j][3] + bias.y);
        }
    }
}

// ---------------- conv: 128-edge x 64-out tile, 3xTF32 mma + v2 atomics -----
#define CONV_SMEM_FLOATS (TC_SMEM_FLOATS + 128 * 3 + 33)
#define CONV_SMEM_BYTES (CONV_SMEM_FLOATS * 4)

__global__ __launch_bounds__(256, 2) void k_conv(
    const float* __restrict__ x, const void* __restrict__ ei,
    const float* __restrict__ wf, const float* __restrict__ wb,
    float* __restrict__ out)
{
    extern __shared__ float sm[];
    float* Ah  = sm;
    float* Al  = sm + 8192;
    float* Bth = sm + 16384;
    float* Btl = sm + 20480;
    int*   Ss  = (int*)(sm + 24576);
    int*   Ds  = Ss + 128;
    float* Cs  = (float*)(Ds + 128);
    int*   Tst = (int*)(Cs + 128);

    int tid = threadIdx.x;
    int dir = blockIdx.y;
    int tile = blockIdx.x;

    if (tid < 32) {
        int nt = (G.hist[tid] + 127) >> 7;
        int a = nt;
        #pragma unroll
        for (int o = 1; o < 32; o <<= 1) {
            int v = __shfl_up_sync(0xFFFFFFFFu, a, o);
            if (tid >= o) a += v;
        }
        Tst[tid] = a - nt;
        if (tid == 31) Tst[32] = a;
    }
    __syncthreads();
    if (tile >= Tst[32]) return;

    int r = 0;
    while (r < 31 && Tst[r + 1] <= tile) r++;
    float inv = g_inv[dir][r];
    int is64 = g_is64;

    // edge metadata
    if (tid < 128) {
        int ep = G.order[tile * 128 + tid];
        int s = 0, d = -1; float c = 0.f;
        if (ep > 0) {
            int e = ep - 1;
            int a = load_idx(ei, e, is64);
            int b2 = load_idx(ei, N_EDGES + e, is64);
            if (dir) { int t = a; a = b2; b2 = t; }
            s = a; d = b2;
            int cnt = dir ? G.cnt_dst[s] : G.cnt_src[s];
            c = inv / (float)(cnt + 1);
        }
        Ss[tid] = s; Ds[tid] = d; Cs[tid] = c;
    }
    __syncthreads();

    // B = W_r ([k][n] in gmem) -> Bt[n][k] swizzled hi/lo
    {
        const float4* w4 = (const float4*)((dir ? wb : wf) + (size_t)r * (C * C));
        #pragma unroll
        for (int q = 0; q < 4; q++) {
            int i4 = tid + 256 * q;
            float4 v = w4[i4];                 // k = i4>>4, n = (i4&15)*4 ..+3
            int k = i4 >> 4;
            int n0 = (i4 & 15) * 4;
            float f[4] = {v.x, v.y, v.z, v.w};
            #pragma unroll
            for (int i = 0; i < 4; i++) {
                int n = n0 + i;
                float hi, lo;
                split_tf(f[i], hi, lo);
                Bth[SWZ(n, k)] = hi;
                Btl[SWZ(n, k)] = lo;
            }
        }
    }
    // gather A rows (unscaled x), split hi/lo
    {
        int m = tid & 127, h = tid >> 7;
        const float4* xr = (const float4*)(x + (size_t)Ss[m] * C + h * 32);
        #pragma unroll
        for (int q = 0; q < 8; q++) {
            float4 v = xr[q];
            int kg = h * 8 + q;
            int pg = kg ^ (m & 7);
            float4 hi, lo;
            split_tf(v.x, hi.x, lo.x); split_tf(v.y, hi.y, lo.y);
            split_tf(v.z, hi.z, lo.z); split_tf(v.w, hi.w, lo.w);
            *(float4*)&Ah[m * 64 + pg * 4] = hi;
            *(float4*)&Al[m * 64 + pg * 4] = lo;
        }
    }
    __syncthreads();

    int lane = tid & 31, w = tid >> 5;
    int gid = lane >> 2, tig = lane & 3;
    int m0 = w * 16;
    float d[8][4] = {};
    #pragma unroll
    for (int s8 = 0; s8 < 8; s8++) {
        int kg = 2 * s8;
        int mA = m0 + gid, xa = mA & 7;
        unsigned ah0 = __float_as_uint(Ah[mA * 64 + ((kg ^ xa) << 2) + tig]);
        unsigned ah1 = __float_as_uint(Ah[(mA + 8) * 64 + ((kg ^ xa) << 2) + tig]);
        unsigned ah2 = __float_as_uint(Ah[mA * 64 + (((kg + 1) ^ xa) << 2) + tig]);
        unsigned ah3 = __float_as_uint(Ah[(mA + 8) * 64 + (((kg + 1) ^ xa) << 2) + tig]);
        unsigned al0 = __float_as_uint(Al[mA * 64 + ((kg ^ xa) << 2) + tig]);
        unsigned al1 = __float_as_uint(Al[(mA + 8) * 64 + ((kg ^ xa) << 2) + tig]);
        unsigned al2 = __float_as_uint(Al[mA * 64 + (((kg + 1) ^ xa) << 2) + tig]);
        unsigned al3 = __float_as_uint(Al[(mA + 8) * 64 + (((kg + 1) ^ xa) << 2) + tig]);
        #pragma unroll
        for (int j = 0; j < 8; j++) {
            int nB = j * 8 + gid;
            unsigned bh0 = __float_as_uint(Bth[nB * 64 + ((kg ^ gid) << 2) + tig]);
            unsigned bh1 = __float_as_uint(Bth[nB * 64 + (((kg + 1) ^ gid) << 2) + tig]);
            unsigned bl0 = __float_as_uint(Btl[nB * 64 + ((kg ^ gid) << 2) + tig]);
            unsigned bl1 = __float_as_uint(Btl[nB * 64 + (((kg + 1) ^ gid) << 2) + tig]);
            mma_tf32(d[j], ah0, ah1, ah2, ah3, bh0, bh1);
            mma_tf32(d[j], al0, al1, al2, al3, bh0, bh1);
            mma_tf32(d[j], ah0, ah1, ah2, ah3, bl0, bl1);
        }
    }

    // epilogue: scale by per-edge coef, vector atomic scatter
    int r0 = m0 + gid, r1 = r0 + 8;
    int d0i = Ds[r0], d1i = Ds[r1];
    float c0 = Cs[r0], c1 = Cs[r1];
    #pragma unroll
    for (int j = 0; j < 8; j++) {
        int n = j * 8 + 2 * tig;
        if (d0i >= 0)
            red2(out + (size_t)d0i * C + n, d[j][0] * c0, d[j][1] * c0);
        if (d1i >= 0)
            red2(out + (size_t)d1i * C + n, d[j][2] * c1, d[j][3] * c1);
    }
}

// ---------------- launch ----------------
extern "C" void kernel_launch(void* const* d_in, const int* in_sizes, int n_in,
                              void* d_out, int out_size)
{
    const float* x  = (const float*)d_in[0];
    const void*  ei = d_in[1];
    const void*  et = d_in[2];
    const float* wf = (const float*)d_in[3];
    const float* wb = (const float*)d_in[4];
    const float* lw = (const float*)d_in[5];
    const float* lb = (const float*)d_in[6];
    float* out = (float*)d_out;

    cudaFuncSetAttribute(k_conv, cudaFuncAttributeMaxDynamicSharedMemorySize,
                         CONV_SMEM_BYTES);
    cudaFuncSetAttribute(k_scatlin, cudaFuncAttributeMaxDynamicSharedMemorySize,
                         SCAT_SMEM_BYTES);

    const int zero_blocks = (int)((sizeof(GScratch) / 16 + 255) / 256);
    k_prep<<<64 + 1 + zero_blocks, 256>>>(wf, wb, ei);
    k_count<<<(N_EDGES + 255) / 256, 256>>>(ei, et);
    k_scatlin<<<SCAT_BLOCKS + LIN_BLOCKS, 256, SCAT_SMEM_BYTES>>>(et, x, lw, lb, out);
    dim3 g(MAXTILES, 2);
    k_conv<<<g, 256, CONV_SMEM_BYTES>>>(x, ei, wf, wb, out);
}

// round 4
// speedup vs baseline: 1.5643x; 1.0385x over previous
#include <cuda_runtime.h>
#include <math.h>

#define N_NODES 20000
#define N_EDGES 50000
#define C 64
#define NREL 32
#define MAXTILES 424                 // >= 50000/128 + 32
#define ORDER_CAP (MAXTILES * 128)   // 54272

// ---------------- scratch (no allocations allowed) ----------------
struct __align__(16) GScratch {
    int cnt_src[N_NODES];
    int cnt_dst[N_NODES];
    int hist[NREL];
    int cursor[NREL];
    int order[ORDER_CAP];            // stores e+1; 0 = empty/pad
};
__device__ GScratch G;
__device__ float g_inv[2][NREL];
__device__ int g_is64;

__device__ __forceinline__ int load_idx(const void* p, int i, int is64) {
    return is64 ? (int)((const long long*)p)[i] : ((const int*)p)[i];
}
__device__ __forceinline__ unsigned f2tf(float f) {
    unsigned u; asm("cvt.rna.tf32.f32 %0, %1;" : "=r"(u) : "f"(f)); return u;
}
__device__ __forceinline__ void split_tf(float v, float& hi, float& lo) {
    float h = __uint_as_float(f2tf(v));
    hi = h;
    lo = __uint_as_float(f2tf(v - h));
}
__device__ __forceinline__ void mma_tf32(float* d,
    unsigned a0, unsigned a1, unsigned a2, unsigned a3,
    unsigned b0, unsigned b1)
{
    asm volatile(
        "mma.sync.aligned.m16n8k8.row.col.f32.tf32.tf32.f32 "
        "{%0,%1,%2,%3},{%4,%5,%6,%7},{%8,%9},{%0,%1,%2,%3};"
        : "+f"(d[0]), "+f"(d[1]), "+f"(d[2]), "+f"(d[3])
        : "r"(a0), "r"(a1), "r"(a2), "r"(a3), "r"(b0), "r"(b1));
}
__device__ __forceinline__ void ldsm4(unsigned& r0, unsigned& r1,
                                      unsigned& r2, unsigned& r3, unsigned addr)
{
    asm volatile("ldmatrix.sync.aligned.m8n8.x4.shared.b16 {%0,%1,%2,%3}, [%4];"
                 : "=r"(r0), "=r"(r1), "=r"(r2), "=r"(r3) : "r"(addr));
}
__device__ __forceinline__ void red2(float* p, float a, float b) {
    asm volatile("red.global.add.v2.f32 [%0], {%1, %2};"
                 :: "l"(p), "f"(a), "f"(b) : "memory");
}
// swizzled index for [rows][64] arrays: element (m,k)
#define SWZ(m, k) ((m) * 64 + ((((k) >> 2) ^ ((m) & 7)) << 2) + ((k) & 3))

// ---------------- prep ------------------------------------------------------
__global__ __launch_bounds__(256) void k_prep(
    const float* __restrict__ wf, const float* __restrict__ wb,
    const void* __restrict__ ei)
{
    int b = blockIdx.x, tid = threadIdx.x;
    if (b < 64) {
        __shared__ float red[256];
        int r = b & 31, tab = b >> 5;
        const float* w = (tab ? wb : wf) + (size_t)r * (C * C);
        float s = 0.f;
        for (int j = tid; j < C * C; j += 256) { float v = w[j]; s += v * v; }
        red[tid] = s; __syncthreads();
        for (int o = 128; o > 0; o >>= 1) {
            if (tid < o) red[tid] += red[tid + o];
            __syncthreads();
        }
        if (tid == 0) g_inv[tab][r] = 1.f / (sqrtf(red[0]) + 0.01f);
    } else if (b == 64) {
        if (tid < 32) {
            int hi = ((const int*)ei)[2 * tid + 1];
            unsigned ok = __ballot_sync(0xFFFFFFFFu, hi == 0);
            if (tid == 0) g_is64 = (ok == 0xFFFFFFFFu) ? 1 : 0;
        }
    } else {
        int i = (b - 65) * 256 + tid;
        const int n16 = (int)(sizeof(GScratch) / 16);
        if (i < n16) ((int4*)&G)[i] = make_int4(0, 0, 0, 0);
    }
}

// ---------------- count -----------------------------------------------------
__global__ __launch_bounds__(256) void k_count(
    const void* __restrict__ ei, const void* __restrict__ et)
{
    __shared__ int h[NREL];
    int tid = threadIdx.x;
    if (tid < NREL) h[tid] = 0;
    __syncthreads();
    int e = blockIdx.x * 256 + tid;
    int is64 = g_is64;
    if (e < N_EDGES) {
        atomicAdd(&G.cnt_src[load_idx(ei, e, is64)], 1);
        atomicAdd(&G.cnt_dst[load_idx(ei, N_EDGES + e, is64)], 1);
        atomicAdd(&h[load_idx(et, e, is64)], 1);
    }
    __syncthreads();
    if (tid < NREL && h[tid]) atomicAdd(&G.hist[tid], h[tid]);
}

// ============ shared tensor-core inner loop (128x64 @ k=64, 3xTF32) =========
// Ah/Al: 128x64 swizzled; Bth/Btl: 64x64 swizzled (n-major). d[8][4] out.
__device__ __forceinline__ void mma_main(
    unsigned sAh, unsigned sAl, unsigned sBh, unsigned sBl,
    int lane, int warp, float d[8][4])
{
    // per-thread ldmatrix row addressing
    int mA  = warp * 16 + (lane & 15);
    unsigned aconst = mA * 256u;
    unsigned ahx = (unsigned)(((lane >> 4) ^ (mA & 7)) & 15);
    int nr  = ((lane & 16) >> 1) + (lane & 7);
    unsigned bconst = nr * 256u;
    unsigned bhx = (unsigned)((((lane >> 3) & 1) ^ (lane & 7)) & 15);

    #pragma unroll
    for (int s8 = 0; s8 < 8; s8++) {
        unsigned kg = 2 * s8;
        unsigned aoff = ((kg ^ ahx) & 15u) << 4;
        unsigned ah0, ah1, ah2, ah3, al0, al1, al2, al3;
        ldsm4(ah0, ah1, ah2, ah3, sAh + aconst + aoff);
        ldsm4(al0, al1, al2, al3, sAl + aconst + aoff);
        unsigned boff = ((kg ^ bhx) & 15u) << 4;
        #pragma unroll
        for (int jj = 0; jj < 4; jj++) {
            unsigned badd = bconst + jj * 16u * 256u + boff;
            unsigned bh0, bh1, bh2, bh3, bl0, bl1, bl2, bl3;
            ldsm4(bh0, bh1, bh2, bh3, sBh + badd);
            ldsm4(bl0, bl1, bl2, bl3, sBl + badd);
            mma_tf32(d[2 * jj],     ah0, ah1, ah2, ah3, bh0, bh1);
            mma_tf32(d[2 * jj],     al0, al1, al2, al3, bh0, bh1);
            mma_tf32(d[2 * jj],     ah0, ah1, ah2, ah3, bl0, bl1);
            mma_tf32(d[2 * jj + 1], ah0, ah1, ah2, ah3, bh2, bh3);
            mma_tf32(d[2 * jj + 1], al0, al1, al2, al3, bh2, bh3);
            mma_tf32(d[2 * jj + 1], ah0, ah1, ah2, ah3, bl2, bl3);
        }
    }
}

// ---------------- scatter + linear term -------------------------------------
#define SCAT_BLOCKS 196
#define LIN_BLOCKS ((N_NODES + 127) / 128)
#define TC_SMEM_FLOATS (8192 + 8192 + 4096 + 4096)
#define SCAT_SMEM_BYTES (TC_SMEM_FLOATS * 4)

__global__ __launch_bounds__(256, 3) void k_scatlin(
    const void* __restrict__ et, const float* __restrict__ x,
    const float* __restrict__ lw, const float* __restrict__ lb,
    float* __restrict__ out)
{
    int tid = threadIdx.x;
    if (blockIdx.x < SCAT_BLOCKS) {
        __shared__ int obase[NREL];
        __shared__ int bcnt[NREL];
        __shared__ int gbase[NREL];
        if (tid < 32) {
            int nt = (G.hist[tid] + 127) >> 7;
            int a = nt;
            #pragma unroll
            for (int o = 1; o < 32; o <<= 1) {
                int v = __shfl_up_sync(0xFFFFFFFFu, a, o);
                if (tid >= o) a += v;
            }
            obase[tid] = (a - nt) * 128;
            bcnt[tid] = 0;
        }
        __syncthreads();
        int e = blockIdx.x * 256 + tid;
        int r = 0, my = 0, valid = (e < N_EDGES);
        if (valid) {
            r = load_idx(et, e, g_is64);
            my = atomicAdd(&bcnt[r], 1);
        }
        __syncthreads();
        if (tid < 32 && bcnt[tid]) gbase[tid] = atomicAdd(&G.cursor[tid], bcnt[tid]);
        __syncthreads();
        if (valid) G.order[obase[r] + gbase[r] + my] = e + 1;
        return;
    }

    extern __shared__ float sm[];
    float* Ah  = sm;
    float* Al  = sm + 8192;
    float* Bth = sm + 16384;
    float* Btl = sm + 20480;
    unsigned sbase = (unsigned)__cvta_generic_to_shared(sm);
    unsigned sAh = sbase, sAl = sbase + 8192 * 4;
    unsigned sBh = sbase + 16384 * 4, sBl = sbase + 20480 * 4;

    int node0 = (blockIdx.x - SCAT_BLOCKS) * 128;

    {   // B = lw (row n, col k) -> Bt[n][k] swizzled hi/lo
        const float4* w4 = (const float4*)lw;
        #pragma unroll
        for (int q = 0; q < 4; q++) {
            int i4 = tid + 256 * q;
            float4 v = w4[i4];
            int n = i4 >> 4;
            int pg = (i4 & 15) ^ (n & 7);
            float4 hi, lo;
            split_tf(v.x, hi.x, lo.x); split_tf(v.y, hi.y, lo.y);
            split_tf(v.z, hi.z, lo.z); split_tf(v.w, hi.w, lo.w);
            *(float4*)&Bth[n * 64 + pg * 4] = hi;
            *(float4*)&Btl[n * 64 + pg * 4] = lo;
        }
    }
    {   // A = x rows
        int m = tid & 127, h = tid >> 7;
        int node = node0 + m;
        if (node >= N_NODES) node = 0;
        const float4* xr = (const float4*)(x + (size_t)node * C + h * 32);
        #pragma unroll
        for (int q = 0; q < 8; q++) {
            float4 v = xr[q];
            int pg = (h * 8 + q) ^ (m & 7);
            float4 hi, lo;
            split_tf(v.x, hi.x, lo.x); split_tf(v.y, hi.y, lo.y);
            split_tf(v.z, hi.z, lo.z); split_tf(v.w, hi.w, lo.w);
            *(float4*)&Ah[m * 64 + pg * 4] = hi;
            *(float4*)&Al[m * 64 + pg * 4] = lo;
        }
    }
    __syncthreads();

    int lane = tid & 31, w = tid >> 5;
    float d[8][4] = {};
    mma_main(sAh, sAl, sBh, sBl, lane, w, d);

    int gid = lane >> 2, tig = lane & 3;
    int r0 = w * 16 + gid, r1 = r0 + 8;
    #pragma unroll
    for (int j = 0; j < 8; j++) {
        int n = j * 8 + 2 * tig;
        float2 bias = *(const float2*)(lb + n);
        if (node0 + r0 < N_NODES)
            *(float2*)(out + (size_t)(node0 + r0) * C + n) =
                make_float2(d[j][0] + bias.x, d[j][1] + bias.y);
        if (node0 + r1 < N_NODES)
            *(float2*)(out + (size_t)(node0 + r1) * C + n) =
                make_float2(d[j][2] + bias.x, d[j][3] + bias.y);
    }
}

// ---------------- conv ------------------------------------------------------
#define CONV_SMEM_FLOATS (TC_SMEM_FLOATS + 128 * 3 + 33)
#define CONV_SMEM_BYTES (CONV_SMEM_FLOATS * 4)

__global__ __launch_bounds__(256, 3) void k_conv(
    const float* __restrict__ x, const void* __restrict__ ei,
    const float* __restrict__ wf, const float* __restrict__ wb,
    float* __restrict__ out)
{
    extern __shared__ float sm[];
    float* Ah  = sm;
    float* Al  = sm + 8192;
    float* Bth = sm + 16384;
    float* Btl = sm + 20480;
    int*   Ss  = (int*)(sm + 24576);
    int*   Ds  = Ss + 128;
    float* Cs  = (float*)(Ds + 128);
    int*   Tst = (int*)(Cs + 128);
    unsigned sbase = (unsigned)__cvta_generic_to_shared(sm);
    unsigned sAh = sbase, sAl = sbase + 8192 * 4;
    unsigned sBh = sbase + 16384 * 4, sBl = sbase + 20480 * 4;

    int tid = threadIdx.x;
    int dir = blockIdx.y;
    int tile = blockIdx.x;

    if (tid < 32) {
        int nt = (G.hist[tid] + 127) >> 7;
        int a = nt;
        #pragma unroll
        for (int o = 1; o < 32; o <<= 1) {
            int v = __shfl_up_sync(0xFFFFFFFFu, a, o);
            if (tid >= o) a += v;
        }
        Tst[tid] = a - nt;
        if (tid == 31) Tst[32] = a;
    }
    __syncthreads();
    if (tile >= Tst[32]) return;

    int r = 0;
    while (r < 31 && Tst[r + 1] <= tile) r++;
    float inv = g_inv[dir][r];
    int is64 = g_is64;

    if (tid < 128) {
        int ep = G.order[tile * 128 + tid];
        int s = 0, d = -1; float c = 0.f;
        if (ep > 0) {
            int e = ep - 1;
            int a = load_idx(ei, e, is64);
            int b2 = load_idx(ei, N_EDGES + e, is64);
            if (dir) { int t = a; a = b2; b2 = t; }
            s = a; d = b2;
            int cnt = dir ? G.cnt_dst[s] : G.cnt_src[s];
            c = inv / (float)(cnt + 1);
        }
        Ss[tid] = s; Ds[tid] = d; Cs[tid] = c;
    }
    __syncthreads();

    {   // B = W_r ([k][n] gmem) -> Bt[n][k] swizzled hi/lo
        const float4* w4 = (const float4*)((dir ? wb : wf) + (size_t)r * (C * C));
        #pragma unroll
        for (int q = 0; q < 4; q++) {
            int i4 = tid + 256 * q;
            float4 v = w4[i4];
            int k = i4 >> 4;
            int n0 = (i4 & 15) * 4;
            float f[4] = {v.x, v.y, v.z, v.w};
            #pragma unroll
            for (int i = 0; i < 4; i++) {
                int n = n0 + i;
                float hi, lo;
                split_tf(f[i], hi, lo);
                Bth[SWZ(n, k)] = hi;
                Btl[SWZ(n, k)] = lo;
            }
        }
    }
    {   // gather A rows (unscaled x)
        int m = tid & 127, h = tid >> 7;
        const float4* xr = (const float4*)(x + (size_t)Ss[m] * C + h * 32);
        #pragma unroll
        for (int q = 0; q < 8; q++) {
            float4 v = xr[q];
            int pg = (h * 8 + q) ^ (m & 7);
            float4 hi, lo;
            split_tf(v.x, hi.x, lo.x); split_tf(v.y, hi.y, lo.y);
            split_tf(v.z, hi.z, lo.z); split_tf(v.w, hi.w, lo.w);
            *(float4*)&Ah[m * 64 + pg * 4] = hi;
            *(float4*)&Al[m * 64 + pg * 4] = lo;
        }
    }
    __syncthreads();

    int lane = tid & 31, w = tid >> 5;
    float d[8][4] = {};
    mma_main(sAh, sAl, sBh, sBl, lane, w, d);

    int gid = lane >> 2, tig = lane & 3;
    int r0 = w * 16 + gid, r1 = r0 + 8;
    int d0i = Ds[r0], d1i = Ds[r1];
    float c0 = Cs[r0], c1 = Cs[r1];
    #pragma unroll
    for (int j = 0; j < 8; j++) {
        int n = j * 8 + 2 * tig;
        if (d0i >= 0)
            red2(out + (size_t)d0i * C + n, d[j][0] * c0, d[j][1] * c0);
        if (d1i >= 0)
            red2(out + (size_t)d1i * C + n, d[j][2] * c1, d[j][3] * c1);
    }
}

// ---------------- launch ----------------
extern "C" void kernel_launch(void* const* d_in, const int* in_sizes, int n_in,
                              void* d_out, int out_size)
{
    const float* x  = (const float*)d_in[0];
    const void*  ei = d_in[1];
    const void*  et = d_in[2];
    const float* wf = (const float*)d_in[3];
    const float* wb = (const float*)d_in[4];
    const float* lw = (const float*)d_in[5];
    const float* lb = (const float*)d_in[6];
    float* out = (float*)d_out;

    cudaFuncSetAttribute(k_conv, cudaFuncAttributeMaxDynamicSharedMemorySize,
                         CONV_SMEM_BYTES);
    cudaFuncSetAttribute(k_scatlin, cudaFuncAttributeMaxDynamicSharedMemorySize,
                         SCAT_SMEM_BYTES);

    const int zero_blocks = (int)((sizeof(GScratch) / 16 + 255) / 256);
    k_prep<<<64 + 1 + zero_blocks, 256>>>(wf, wb, ei);
    k_count<<<(N_EDGES + 255) / 256, 256>>>(ei, et);
    k_scatlin<<<SCAT_BLOCKS + LIN_BLOCKS, 256, SCAT_SMEM_BYTES>>>(et, x, lw, lb, out);
    dim3 g(MAXTILES, 2);
    k_conv<<<g, 256, CONV_SMEM_BYTES>>>(x, ei, wf, wb, out);
}

// round 5
// speedup vs baseline: 1.6341x; 1.0446x over previous
#include <cuda_runtime.h>
#include <math.h>

#define N_NODES 20000
#define N_EDGES 50000
#define C 64
#define NREL 32
#define MAXTILES 424                 // >= 50000/128 + 32
#define ORDER_CAP (MAXTILES * 128)   // 54272

// ---------------- scratch (no allocations allowed) ----------------
struct __align__(16) GScratch {
    int cnt_src[N_NODES];
    int cnt_dst[N_NODES];
    int hist[NREL];
    int cursor[NREL];
    int order[ORDER_CAP];            // stores e+1; 0 = empty/pad
};
__device__ GScratch G;
__device__ float g_inv[2][NREL];
__device__ int g_is64;

__device__ __forceinline__ int load_idx(const void* p, int i, int is64) {
    return is64 ? (int)((const long long*)p)[i] : ((const int*)p)[i];
}
__device__ __forceinline__ unsigned f2tf(float f) {
    unsigned u; asm("cvt.rna.tf32.f32 %0, %1;" : "=r"(u) : "f"(f)); return u;
}
__device__ __forceinline__ void split_tf(float v, float& hi, float& lo) {
    float h = __uint_as_float(f2tf(v));
    hi = h;
    lo = __uint_as_float(f2tf(v - h));
}
__device__ __forceinline__ void mma_tf32(float* d,
    unsigned a0, unsigned a1, unsigned a2, unsigned a3,
    unsigned b0, unsigned b1)
{
    asm volatile(
        "mma.sync.aligned.m16n8k8.row.col.f32.tf32.tf32.f32 "
        "{%0,%1,%2,%3},{%4,%5,%6,%7},{%8,%9},{%0,%1,%2,%3};"
        : "+f"(d[0]), "+f"(d[1]), "+f"(d[2]), "+f"(d[3])
        : "r"(a0), "r"(a1), "r"(a2), "r"(a3), "r"(b0), "r"(b1));
}
__device__ __forceinline__ void ldsm4(unsigned& r0, unsigned& r1,
                                      unsigned& r2, unsigned& r3, unsigned addr)
{
    asm volatile("ldmatrix.sync.aligned.m8n8.x4.shared.b16 {%0,%1,%2,%3}, [%4];"
                 : "=r"(r0), "=r"(r1), "=r"(r2), "=r"(r3) : "r"(addr));
}
__device__ __forceinline__ void red4(float* p, float a, float b, float c, float d) {
    asm volatile("red.global.add.v4.f32 [%0], {%1,%2,%3,%4};"
                 :: "l"(p), "f"(a), "f"(b), "f"(c), "f"(d) : "memory");
}
__device__ __forceinline__ void cpa16(unsigned dst, const void* src) {
    asm volatile("cp.async.ca.shared.global [%0], [%1], 16;"
                 :: "r"(dst), "l"(src) : "memory");
}
// swizzled index for [rows][64] arrays: element (m,k)
#define SWZ(m, k) ((m) * 64 + ((((k) >> 2) ^ ((m) & 7)) << 2) + ((k) & 3))

// ---------------- prep ------------------------------------------------------
__global__ __launch_bounds__(256) void k_prep(
    const float* __restrict__ wf, const float* __restrict__ wb,
    const void* __restrict__ ei)
{
    int b = blockIdx.x, tid = threadIdx.x;
    if (b < 64) {
        __shared__ float red[256];
        int r = b & 31, tab = b >> 5;
        const float* w = (tab ? wb : wf) + (size_t)r * (C * C);
        float s = 0.f;
        for (int j = tid; j < C * C; j += 256) { float v = w[j]; s += v * v; }
        red[tid] = s; __syncthreads();
        for (int o = 128; o > 0; o >>= 1) {
            if (tid < o) red[tid] += red[tid + o];
            __syncthreads();
        }
        if (tid == 0) g_inv[tab][r] = 1.f / (sqrtf(red[0]) + 0.01f);
    } else if (b == 64) {
        if (tid < 32) {
            int hi = ((const int*)ei)[2 * tid + 1];
            unsigned ok = __ballot_sync(0xFFFFFFFFu, hi == 0);
            if (tid == 0) g_is64 = (ok == 0xFFFFFFFFu) ? 1 : 0;
        }
    } else {
        int i = (b - 65) * 256 + tid;
        const int n16 = (int)(sizeof(GScratch) / 16);
        if (i < n16) ((int4*)&G)[i] = make_int4(0, 0, 0, 0);
    }
}

// ---------------- count -----------------------------------------------------
__global__ __launch_bounds__(256) void k_count(
    const void* __restrict__ ei, const void* __restrict__ et)
{
    __shared__ int h[NREL];
    int tid = threadIdx.x;
    if (tid < NREL) h[tid] = 0;
    __syncthreads();
    int e = blockIdx.x * 256 + tid;
    int is64 = g_is64;
    if (e < N_EDGES) {
        atomicAdd(&G.cnt_src[load_idx(ei, e, is64)], 1);
        atomicAdd(&G.cnt_dst[load_idx(ei, N_EDGES + e, is64)], 1);
        atomicAdd(&h[load_idx(et, e, is64)], 1);
    }
    __syncthreads();
    if (tid < NREL && h[tid]) atomicAdd(&G.hist[tid], h[tid]);
}

// ====== tensor-core inner loop: A raw fp32 in smem, split in registers ======
// A: 128x64 raw swizzled; Bth/Btl: 64x64 swizzled (n-major). d[8][4] out.
__device__ __forceinline__ void mma_main(
    unsigned sA, unsigned sBh, unsigned sBl,
    int lane, int warp, float d[8][4])
{
    int mA  = warp * 16 + (lane & 15);
    unsigned aconst = mA * 256u;
    unsigned ahx = (unsigned)(((lane >> 4) ^ (mA & 7)) & 15);
    int nr  = ((lane & 16) >> 1) + (lane & 7);
    unsigned bconst = nr * 256u;
    unsigned bhx = (unsigned)((((lane >> 3) & 1) ^ (lane & 7)) & 15);

    #pragma unroll
    for (int s8 = 0; s8 < 8; s8++) {
        unsigned kg = 2 * s8;
        unsigned a0u, a1u, a2u, a3u;
        ldsm4(a0u, a1u, a2u, a3u, sA + aconst + (((kg ^ ahx) & 15u) << 4));
        float h0, l0, h1, l1, h2, l2, h3, l3;
        split_tf(__uint_as_float(a0u), h0, l0);
        split_tf(__uint_as_float(a1u), h1, l1);
        split_tf(__uint_as_float(a2u), h2, l2);
        split_tf(__uint_as_float(a3u), h3, l3);
        unsigned ah0 = __float_as_uint(h0), al0 = __float_as_uint(l0);
        unsigned ah1 = __float_as_uint(h1), al1 = __float_as_uint(l1);
        unsigned ah2 = __float_as_uint(h2), al2 = __float_as_uint(l2);
        unsigned ah3 = __float_as_uint(h3), al3 = __float_as_uint(l3);
        unsigned boff = ((kg ^ bhx) & 15u) << 4;
        #pragma unroll
        for (int jj = 0; jj < 4; jj++) {
            unsigned badd = bconst + jj * 16u * 256u + boff;
            unsigned bh0, bh1, bh2, bh3, bl0, bl1, bl2, bl3;
            ldsm4(bh0, bh1, bh2, bh3, sBh + badd);
            ldsm4(bl0, bl1, bl2, bl3, sBl + badd);
            mma_tf32(d[2 * jj],     ah0, ah1, ah2, ah3, bh0, bh1);
            mma_tf32(d[2 * jj],     al0, al1, al2, al3, bh0, bh1);
            mma_tf32(d[2 * jj],     ah0, ah1, ah2, ah3, bl0, bl1);
            mma_tf32(d[2 * jj + 1], ah0, ah1, ah2, ah3, bh2, bh3);
            mma_tf32(d[2 * jj + 1], al0, al1, al2, al3, bh2, bh3);
            mma_tf32(d[2 * jj + 1], ah0, ah1, ah2, ah3, bl2, bl3);
        }
    }
}

// ---------------- scatter + linear term -------------------------------------
#define SCAT_BLOCKS 196
#define LIN_BLOCKS ((N_NODES + 127) / 128)
#define TC_SMEM_FLOATS (8192 + 4096 + 4096)       // A raw + Bh + Bl = 64KB
#define SCAT_SMEM_BYTES (TC_SMEM_FLOATS * 4)

__global__ __launch_bounds__(256, 3) void k_scatlin(
    const void* __restrict__ et, const float* __restrict__ x,
    const float* __restrict__ lw, const float* __restrict__ lb,
    float* __restrict__ out)
{
    int tid = threadIdx.x;
    if (blockIdx.x < SCAT_BLOCKS) {
        __shared__ int obase[NREL];
        __shared__ int bcnt[NREL];
        __shared__ int gbase[NREL];
        if (tid < 32) {
            int nt = (G.hist[tid] + 127) >> 7;
            int a = nt;
            #pragma unroll
            for (int o = 1; o < 32; o <<= 1) {
                int v = __shfl_up_sync(0xFFFFFFFFu, a, o);
                if (tid >= o) a += v;
            }
            obase[tid] = (a - nt) * 128;
            bcnt[tid] = 0;
        }
        __syncthreads();
        int e = blockIdx.x * 256 + tid;
        int r = 0, my = 0, valid = (e < N_EDGES);
        if (valid) {
            r = load_idx(et, e, g_is64);
            my = atomicAdd(&bcnt[r], 1);
        }
        __syncthreads();
        if (tid < 32 && bcnt[tid]) gbase[tid] = atomicAdd(&G.cursor[tid], bcnt[tid]);
        __syncthreads();
        if (valid) G.order[obase[r] + gbase[r] + my] = e + 1;
        return;
    }

    extern __shared__ float sm[];
    float* Bth = sm + 8192;
    float* Btl = sm + 12288;
    unsigned sbase = (unsigned)__cvta_generic_to_shared(sm);
    unsigned sA = sbase, sBh = sbase + 8192 * 4, sBl = sbase + 12288 * 4;

    int node0 = (blockIdx.x - SCAT_BLOCKS) * 128;

    {   // A = x rows (raw, cp.async into swizzled tile)
        int m = tid & 127, h = tid >> 7;
        int node = node0 + m;
        if (node >= N_NODES) node = 0;
        const float* xr = x + (size_t)node * C + h * 32;
        #pragma unroll
        for (int q = 0; q < 8; q++) {
            int pg = (h * 8 + q) ^ (m & 7);
            cpa16(sA + (unsigned)(m * 64 + pg * 4) * 4u, xr + q * 4);
        }
        asm volatile("cp.async.commit_group;" ::: "memory");
    }
    {   // B = lw (row n, col k) -> Bt[n][k] swizzled hi/lo
        const float4* w4 = (const float4*)lw;
        #pragma unroll
        for (int q = 0; q < 4; q++) {
            int i4 = tid + 256 * q;
            float4 v = w4[i4];
            int n = i4 >> 4;
            int pg = (i4 & 15) ^ (n & 7);
            float4 hi, lo;
            split_tf(v.x, hi.x, lo.x); split_tf(v.y, hi.y, lo.y);
            split_tf(v.z, hi.z, lo.z); split_tf(v.w, hi.w, lo.w);
            *(float4*)&Bth[n * 64 + pg * 4] = hi;
            *(float4*)&Btl[n * 64 + pg * 4] = lo;
        }
    }
    asm volatile("cp.async.wait_group 0;" ::: "memory");
    __syncthreads();

    int lane = tid & 31, w = tid >> 5;
    float d[8][4] = {};
    mma_main(sA, sBh, sBl, lane, w, d);

    int gid = lane >> 2, tig = lane & 3;
    int r0 = w * 16 + gid, r1 = r0 + 8;
    #pragma unroll
    for (int j = 0; j < 8; j++) {
        int n = j * 8 + 2 * tig;
        float2 bias = *(const float2*)(lb + n);
        if (node0 + r0 < N_NODES)
            *(float2*)(out + (size_t)(node0 + r0) * C + n) =
                make_float2(d[j][0] + bias.x, d[j][1] + bias.y);
        if (node0 + r1 < N_NODES)
            *(float2*)(out + (size_t)(node0 + r1) * C + n) =
                make_float2(d[j][2] + bias.x, d[j][3] + bias.y);
    }
}

// ---------------- conv (persistent grid-stride over tile x dir) -------------
#define CONV_SMEM_FLOATS (TC_SMEM_FLOATS + 128 * 3 + 33)
#define CONV_SMEM_BYTES (CONV_SMEM_FLOATS * 4)
#define CONV_GRID (148 * 3)

__global__ __launch_bounds__(256, 3) void k_conv(
    const float* __restrict__ x, const void* __restrict__ ei,
    const float* __restrict__ wf, const float* __restrict__ wb,
    float* __restrict__ out)
{
    extern __shared__ float sm[];
    float* Bth = sm + 8192;
    float* Btl = sm + 12288;
    int*   Ss  = (int*)(sm + 16384);
    int*   Ds  = Ss + 128;
    float* Cs  = (float*)(Ds + 128);
    int*   Tst = (int*)(Cs + 128);
    unsigned sbase = (unsigned)__cvta_generic_to_shared(sm);
    unsigned sA = sbase, sBh = sbase + 8192 * 4, sBl = sbase + 12288 * 4;

    int tid = threadIdx.x;
    int is64 = g_is64;

    if (tid < 32) {
        int nt = (G.hist[tid] + 127) >> 7;
        int a = nt;
        #pragma unroll
        for (int o = 1; o < 32; o <<= 1) {
            int v = __shfl_up_sync(0xFFFFFFFFu, a, o);
            if (tid >= o) a += v;
        }
        Tst[tid] = a - nt;
        if (tid == 31) Tst[32] = a;
    }
    __syncthreads();
    int ntiles = Tst[32];

    for (int work = blockIdx.x; work < 2 * ntiles; work += CONV_GRID) {
        int dir = work >= ntiles;
        int tile = work - dir * ntiles;

        int r = 0;
        while (r < 31 && Tst[r + 1] <= tile) r++;
        float inv = g_inv[dir][r];

        __syncthreads();   // protect Ss/Ds/Cs reuse across loop iterations

        if (tid < 128) {
            int ep = G.order[tile * 128 + tid];
            int s = 0, d = -1; float c = 0.f;
            if (ep > 0) {
                int e = ep - 1;
                int a = load_idx(ei, e, is64);
                int b2 = load_idx(ei, N_EDGES + e, is64);
                if (dir) { int t = a; a = b2; b2 = t; }
                s = a; d = b2;
                int cnt = dir ? G.cnt_dst[s] : G.cnt_src[s];
                c = inv / (float)(cnt + 1);
            }
            Ss[tid] = s; Ds[tid] = d; Cs[tid] = c;
        }
        __syncthreads();

        {   // A rows (raw x) via cp.async, overlapped with B fill below
            int m = tid & 127, h = tid >> 7;
            const float* xr = x + (size_t)Ss[m] * C + h * 32;
            #pragma unroll
            for (int q = 0; q < 8; q++) {
                int pg = (h * 8 + q) ^ (m & 7);
                cpa16(sA + (unsigned)(m * 64 + pg * 4) * 4u, xr + q * 4);
            }
            asm volatile("cp.async.commit_group;" ::: "memory");
        }
        {   // B = W_r ([k][n] gmem) -> Bt[n][k] swizzled hi/lo
            const float4* w4 = (const float4*)((dir ? wb : wf) + (size_t)r * (C * C));
            #pragma unroll
            for (int q = 0; q < 4; q++) {
                int i4 = tid + 256 * q;
                float4 v = w4[i4];
                int k = i4 >> 4;
                int n0 = (i4 & 15) * 4;
                float f[4] = {v.x, v.y, v.z, v.w};
                #pragma unroll
                for (int i = 0; i < 4; i++) {
                    int n = n0 + i;
                    float hi, lo;
                    split_tf(f[i], hi, lo);
                    Bth[SWZ(n, k)] = hi;
                    Btl[SWZ(n, k)] = lo;
                }
            }
        }
        asm volatile("cp.async.wait_group 0;" ::: "memory");
        __syncthreads();

        int lane = tid & 31, w = tid >> 5;
        float d[8][4] = {};
        mma_main(sA, sBh, sBl, lane, w, d);

        // epilogue: scale, pair-combine via shfl, red.v4
        int gid = lane >> 2, tig = lane & 3;
        int r0 = w * 16 + gid, r1 = r0 + 8;
        int d0i = Ds[r0], d1i = Ds[r1];
        float c0 = Cs[r0], c1 = Cs[r1];
        bool lowlane = !(tig & 1);
        #pragma unroll
        for (int j = 0; j < 8; j++) {
            float a0 = d[j][0] * c0, a1 = d[j][1] * c0;
            float b0 = d[j][2] * c1, b1 = d[j][3] * c1;
            float a2 = __shfl_xor_sync(0xFFFFFFFFu, a0, 1);
            float a3 = __shfl_xor_sync(0xFFFFFFFFu, a1, 1);
            float b2 = __shfl_xor_sync(0xFFFFFFFFu, b0, 1);
            float b3 = __shfl_xor_sync(0xFFFFFFFFu, b1, 1);
            if (lowlane) {
                int n = j * 8 + 2 * tig;
                if (d0i >= 0) red4(out + (size_t)d0i * C + n, a0, a1, a2, a3);
                if (d1i >= 0) red4(out + (size_t)d1i * C + n, b0, b1, b2, b3);
            }
        }
    }
}

// ---------------- launch ----------------
extern "C" void kernel_launch(void* const* d_in, const int* in_sizes, int n_in,
                              void* d_out, int out_size)
{
    const float* x  = (const float*)d_in[0];
    const void*  ei = d_in[1];
    const void*  et = d_in[2];
    const float* wf = (const float*)d_in[3];
    const float* wb = (const float*)d_in[4];
    const float* lw = (const float*)d_in[5];
    const float* lb = (const float*)d_in[6];
    float* out = (float*)d_out;

    cudaFuncSetAttribute(k_conv, cudaFuncAttributeMaxDynamicSharedMemorySize,
                         CONV_SMEM_BYTES);
    cudaFuncSetAttribute(k_scatlin, cudaFuncAttributeMaxDynamicSharedMemorySize,
                         SCAT_SMEM_BYTES);

    const int zero_blocks = (int)((sizeof(GScratch) / 16 + 255) / 256);
    k_prep<<<64 + 1 + zero_blocks, 256>>>(wf, wb, ei);
    k_count<<<(N_EDGES + 255) / 256, 256>>>(ei, et);
    k_scatlin<<<SCAT_BLOCKS + LIN_BLOCKS, 256, SCAT_SMEM_BYTES>>>(et, x, lw, lb, out);
    k_conv<<<CONV_GRID, 256, CONV_SMEM_BYTES>>>(x, ei, wf, wb, out);
}

// round 6
// speedup vs baseline: 2.0378x; 1.2471x over previous
#include <cuda_runtime.h>
#include <math.h>

#define N_NODES 20000
#define N_EDGES 50000
#define C 64
#define NREL 32
#define MAXTILES 424                 // >= 50000/128 + 32
#define ORDER_CAP (MAXTILES * 128)   // 54272

// ---------------- scratch (no allocations allowed) ----------------
struct __align__(16) GScratch {
    int cnt_src[N_NODES];
    int cnt_dst[N_NODES];
    int hist[NREL];
    int cursor[NREL];
    int order[ORDER_CAP];            // stores e+1; 0 = empty/pad
};
__device__ GScratch G;
__device__ float g_inv[2][NREL];
__device__ int g_is64;

__device__ __forceinline__ int load_idx(const void* p, int i, int is64) {
    return is64 ? (int)((const long long*)p)[i] : ((const int*)p)[i];
}
__device__ __forceinline__ unsigned f2tf(float f) {
    unsigned u; asm("cvt.rna.tf32.f32 %0, %1;" : "=r"(u) : "f"(f)); return u;
}
__device__ __forceinline__ void mma_tf32(float* d,
    unsigned a0, unsigned a1, unsigned a2, unsigned a3,
    unsigned b0, unsigned b1)
{
    asm volatile(
        "mma.sync.aligned.m16n8k8.row.col.f32.tf32.tf32.f32 "
        "{%0,%1,%2,%3},{%4,%5,%6,%7},{%8,%9},{%0,%1,%2,%3};"
        : "+f"(d[0]), "+f"(d[1]), "+f"(d[2]), "+f"(d[3])
        : "r"(a0), "r"(a1), "r"(a2), "r"(a3), "r"(b0), "r"(b1));
}
__device__ __forceinline__ void ldsm4(unsigned& r0, unsigned& r1,
                                      unsigned& r2, unsigned& r3, unsigned addr)
{
    asm volatile("ldmatrix.sync.aligned.m8n8.x4.shared.b16 {%0,%1,%2,%3}, [%4];"
                 : "=r"(r0), "=r"(r1), "=r"(r2), "=r"(r3) : "r"(addr));
}
__device__ __forceinline__ void red4(float* p, float a, float b, float c, float d) {
    asm volatile("red.global.add.v4.f32 [%0], {%1,%2,%3,%4};"
                 :: "l"(p), "f"(a), "f"(b), "f"(c), "f"(d) : "memory");
}
__device__ __forceinline__ void cpa16(unsigned dst, const void* src) {
    asm volatile("cp.async.ca.shared.global [%0], [%1], 16;"
                 :: "r"(dst), "l"(src) : "memory");
}
// swizzled index for [rows][64] arrays: element (m,k)
#define SWZ(m, k) ((m) * 64 + ((((k) >> 2) ^ ((m) & 7)) << 2) + ((k) & 3))

// ---------------- prep ------------------------------------------------------
__global__ __launch_bounds__(256) void k_prep(
    const float* __restrict__ wf, const float* __restrict__ wb,
    const void* __restrict__ ei)
{
    int b = blockIdx.x, tid = threadIdx.x;
    if (b < 64) {
        __shared__ float red[256];
        int r = b & 31, tab = b >> 5;
        const float* w = (tab ? wb : wf) + (size_t)r * (C * C);
        float s = 0.f;
        for (int j = tid; j < C * C; j += 256) { float v = w[j]; s += v * v; }
        red[tid] = s; __syncthreads();
        for (int o = 128; o > 0; o >>= 1) {
            if (tid < o) red[tid] += red[tid + o];
            __syncthreads();
        }
        if (tid == 0) g_inv[tab][r] = 1.f / (sqrtf(red[0]) + 0.01f);
    } else if (b == 64) {
        if (tid < 32) {
            int hi = ((const int*)ei)[2 * tid + 1];
            unsigned ok = __ballot_sync(0xFFFFFFFFu, hi == 0);
            if (tid == 0) g_is64 = (ok == 0xFFFFFFFFu) ? 1 : 0;
        }
    } else {
        int i = (b - 65) * 256 + tid;
        const int n16 = (int)(sizeof(GScratch) / 16);
        if (i < n16) ((int4*)&G)[i] = make_int4(0, 0, 0, 0);
    }
}

// ---------------- count -----------------------------------------------------
__global__ __launch_bounds__(256) void k_count(
    const void* __restrict__ ei, const void* __restrict__ et)
{
    __shared__ int h[NREL];
    int tid = threadIdx.x;
    if (tid < NREL) h[tid] = 0;
    __syncthreads();
    int e = blockIdx.x * 256 + tid;
    int is64 = g_is64;
    if (e < N_EDGES) {
        atomicAdd(&G.cnt_src[load_idx(ei, e, is64)], 1);
        atomicAdd(&G.cnt_dst[load_idx(ei, N_EDGES + e, is64)], 1);
        atomicAdd(&h[load_idx(et, e, is64)], 1);
    }
    __syncthreads();
    if (tid < NREL && h[tid]) atomicAdd(&G.hist[tid], h[tid]);
}

// ====== tensor-core inner loop: 1xTF32 (rna-rounded in regs) ================
// A: 128x64 raw fp32 swizzled; Bth: 64x64 tf32 swizzled (n-major). d[8][4] out.
__device__ __forceinline__ void mma_main(
    unsigned sA, unsigned sBh, int lane, int warp, float d[8][4])
{
    int mA  = warp * 16 + (lane & 15);
    unsigned aconst = mA * 256u;
    unsigned ahx = (unsigned)(((lane >> 4) ^ (mA & 7)) & 15);
    int nr  = ((lane & 16) >> 1) + (lane & 7);
    unsigned bconst = nr * 256u;
    unsigned bhx = (unsigned)((((lane >> 3) & 1) ^ (lane & 7)) & 15);

    #pragma unroll
    for (int s8 = 0; s8 < 8; s8++) {
        unsigned kg = 2 * s8;
        unsigned a0u, a1u, a2u, a3u;
        ldsm4(a0u, a1u, a2u, a3u, sA + aconst + (((kg ^ ahx) & 15u) << 4));
        unsigned ah0 = f2tf(__uint_as_float(a0u));
        unsigned ah1 = f2tf(__uint_as_float(a1u));
        unsigned ah2 = f2tf(__uint_as_float(a2u));
        unsigned ah3 = f2tf(__uint_as_float(a3u));
        unsigned boff = ((kg ^ bhx) & 15u) << 4;
        #pragma unroll
        for (int jj = 0; jj < 4; jj++) {
            unsigned bh0, bh1, bh2, bh3;
            ldsm4(bh0, bh1, bh2, bh3, sBh + bconst + jj * 16u * 256u + boff);
            mma_tf32(d[2 * jj],     ah0, ah1, ah2, ah3, bh0, bh1);
            mma_tf32(d[2 * jj + 1], ah0, ah1, ah2, ah3, bh2, bh3);
        }
    }
}

// ---------------- scatter + linear term -------------------------------------
#define SCAT_BLOCKS 196
#define LIN_BLOCKS ((N_NODES + 127) / 128)
#define TC_SMEM_FLOATS (8192 + 4096)              // A raw 32KB + Bh 16KB
#define SCAT_SMEM_BYTES (TC_SMEM_FLOATS * 4)

__global__ __launch_bounds__(256, 3) void k_scatlin(
    const void* __restrict__ et, const float* __restrict__ x,
    const float* __restrict__ lw, const float* __restrict__ lb,
    float* __restrict__ out)
{
    int tid = threadIdx.x;
    if (blockIdx.x < SCAT_BLOCKS) {
        __shared__ int obase[NREL];
        __shared__ int bcnt[NREL];
        __shared__ int gbase[NREL];
        if (tid < 32) {
            int nt = (G.hist[tid] + 127) >> 7;
            int a = nt;
            #pragma unroll
            for (int o = 1; o < 32; o <<= 1) {
                int v = __shfl_up_sync(0xFFFFFFFFu, a, o);
                if (tid >= o) a += v;
            }
            obase[tid] = (a - nt) * 128;
            bcnt[tid] = 0;
        }
        __syncthreads();
        int e = blockIdx.x * 256 + tid;
        int r = 0, my = 0, valid = (e < N_EDGES);
        if (valid) {
            r = load_idx(et, e, g_is64);
            my = atomicAdd(&bcnt[r], 1);
        }
        __syncthreads();
        if (tid < 32 && bcnt[tid]) gbase[tid] = atomicAdd(&G.cursor[tid], bcnt[tid]);
        __syncthreads();
        if (valid) G.order[obase[r] + gbase[r] + my] = e + 1;
        return;
    }

    extern __shared__ float sm[];
    float* Bth = sm + 8192;
    unsigned sbase = (unsigned)__cvta_generic_to_shared(sm);
    unsigned sA = sbase, sBh = sbase + 8192 * 4;

    int node0 = (blockIdx.x - SCAT_BLOCKS) * 128;

    {   // A = x rows (raw, cp.async into swizzled tile)
        int m = tid & 127, h = tid >> 7;
        int node = node0 + m;
        if (node >= N_NODES) node = 0;
        const float* xr = x + (size_t)node * C + h * 32;
        #pragma unroll
        for (int q = 0; q < 8; q++) {
            int pg = (h * 8 + q) ^ (m & 7);
            cpa16(sA + (unsigned)(m * 64 + pg * 4) * 4u, xr + q * 4);
        }
        asm volatile("cp.async.commit_group;" ::: "memory");
    }
    {   // B = lw (row n, col k) -> Bt[n][k] swizzled tf32
        const float4* w4 = (const float4*)lw;
        #pragma unroll
        for (int q = 0; q < 4; q++) {
            int i4 = tid + 256 * q;
            float4 v = w4[i4];
            int n = i4 >> 4;
            int pg = (i4 & 15) ^ (n & 7);
            float4 hi;
            hi.x = __uint_as_float(f2tf(v.x));
            hi.y = __uint_as_float(f2tf(v.y));
            hi.z = __uint_as_float(f2tf(v.z));
            hi.w = __uint_as_float(f2tf(v.w));
            *(float4*)&Bth[n * 64 + pg * 4] = hi;
        }
    }
    asm volatile("cp.async.wait_group 0;" ::: "memory");
    __syncthreads();

    int lane = tid & 31, w = tid >> 5;
    float d[8][4] = {};
    mma_main(sA, sBh, lane, w, d);

    int gid = lane >> 2, tig = lane & 3;
    int r0 = w * 16 + gid, r1 = r0 + 8;
    #pragma unroll
    for (int j = 0; j < 8; j++) {
        int n = j * 8 + 2 * tig;
        float2 bias = *(const float2*)(lb + n);
        if (node0 + r0 < N_NODES)
            *(float2*)(out + (size_t)(node0 + r0) * C + n) =
                make_float2(d[j][0] + bias.x, d[j][1] + bias.y);
        if (node0 + r1 < N_NODES)
            *(float2*)(out + (size_t)(node0 + r1) * C + n) =
                make_float2(d[j][2] + bias.x, d[j][3] + bias.y);
    }
}

// ---------------- conv (persistent grid-stride over tile x dir) -------------
#define CONV_SMEM_FLOATS (TC_SMEM_FLOATS + 128 * 3 + 33)
#define CONV_SMEM_BYTES (CONV_SMEM_FLOATS * 4)
#define CONV_GRID (148 * 3)

__global__ __launch_bounds__(256, 3) void k_conv(
    const float* __restrict__ x, const void* __restrict__ ei,
    const float* __restrict__ wf, const float* __restrict__ wb,
    float* __restrict__ out)
{
    extern __shared__ float sm[];
    float* Bth = sm + 8192;
    int*   Ss  = (int*)(sm + 12288);
    int*   Ds  = Ss + 128;
    float* Cs  = (float*)(Ds + 128);
    int*   Tst = (int*)(Cs + 128);
    unsigned sbase = (unsigned)__cvta_generic_to_shared(sm);
    unsigned sA = sbase, sBh = sbase + 8192 * 4;

    int tid = threadIdx.x;
    int is64 = g_is64;

    if (tid < 32) {
        int nt = (G.hist[tid] + 127) >> 7;
        int a = nt;
        #pragma unroll
        for (int o = 1; o < 32; o <<= 1) {
            int v = __shfl_up_sync(0xFFFFFFFFu, a, o);
            if (tid >= o) a += v;
        }
        Tst[tid] = a - nt;
        if (tid == 31) Tst[32] = a;
    }
    __syncthreads();
    int ntiles = Tst[32];

    for (int work = blockIdx.x; work < 2 * ntiles; work += CONV_GRID) {
        int dir = work >= ntiles;
        int tile = work - dir * ntiles;

        int r = 0;
        while (r < 31 && Tst[r + 1] <= tile) r++;
        float inv = g_inv[dir][r];

        __syncthreads();   // protect Ss/Ds/Cs reuse across loop iterations

        if (tid < 128) {
            int ep = G.order[tile * 128 + tid];
            int s = 0, d = -1; float c = 0.f;
            if (ep > 0) {
                int e = ep - 1;
                int a = load_idx(ei, e, is64);
                int b2 = load_idx(ei, N_EDGES + e, is64);
                if (dir) { int t = a; a = b2; b2 = t; }
                s = a; d = b2;
                int cnt = dir ? G.cnt_dst[s] : G.cnt_src[s];
                c = inv / (float)(cnt + 1);
            }
            Ss[tid] = s; Ds[tid] = d; Cs[tid] = c;
        }
        __syncthreads();

        {   // A rows (raw x) via cp.async, overlapped with B fill below
            int m = tid & 127, h = tid >> 7;
            const float* xr = x + (size_t)Ss[m] * C + h * 32;
            #pragma unroll
            for (int q = 0; q < 8; q++) {
                int pg = (h * 8 + q) ^ (m & 7);
                cpa16(sA + (unsigned)(m * 64 + pg * 4) * 4u, xr + q * 4);
            }
            asm volatile("cp.async.commit_group;" ::: "memory");
        }
        {   // B = W_r ([k][n] gmem) -> Bt[n][k] swizzled tf32
            const float4* w4 = (const float4*)((dir ? wb : wf) + (size_t)r * (C * C));
            #pragma unroll
            for (int q = 0; q < 4; q++) {
                int i4 = tid + 256 * q;
                float4 v = w4[i4];
                int k = i4 >> 4;
                int n0 = (i4 & 15) * 4;
                float f[4] = {v.x, v.y, v.z, v.w};
                #pragma unroll
                for (int i = 0; i < 4; i++)
                    Bth[SWZ(n0 + i, k)] = __uint_as_float(f2tf(f[i]));
            }
        }
        asm volatile("cp.async.wait_group 0;" ::: "memory");
        __syncthreads();

        int lane = tid & 31, w = tid >> 5;
        float d[8][4] = {};
        mma_main(sA, sBh, lane, w, d);

        // epilogue: scale, pair-combine via shfl, red.v4
        int gid = lane >> 2, tig = lane & 3;
        int r0 = w * 16 + gid, r1 = r0 + 8;
        int d0i = Ds[r0], d1i = Ds[r1];
        float c0 = Cs[r0], c1 = Cs[r1];
        bool lowlane = !(tig & 1);
        #pragma unroll
        for (int j = 0; j < 8; j++) {
            float a0 = d[j][0] * c0, a1 = d[j][1] * c0;
            float b0 = d[j][2] * c1, b1 = d[j][3] * c1;
            float a2 = __shfl_xor_sync(0xFFFFFFFFu, a0, 1);
            float a3 = __shfl_xor_sync(0xFFFFFFFFu, a1, 1);
            float b2 = __shfl_xor_sync(0xFFFFFFFFu, b0, 1);
            float b3 = __shfl_xor_sync(0xFFFFFFFFu, b1, 1);
            if (lowlane) {
                int n = j * 8 + 2 * tig;
                if (d0i >= 0) red4(out + (size_t)d0i * C + n, a0, a1, a2, a3);
                if (d1i >= 0) red4(out + (size_t)d1i * C + n, b0, b1, b2, b3);
            }
        }
    }
}

// ---------------- launch ----------------
extern "C" void kernel_launch(void* const* d_in, const int* in_sizes, int n_in,
                              void* d_out, int out_size)
{
    const float* x  = (const float*)d_in[0];
    const void*  ei = d_in[1];
    const void*  et = d_in[2];
    const float* wf = (const float*)d_in[3];
    const float* wb = (const float*)d_in[4];
    const float* lw = (const float*)d_in[5];
    const float* lb = (const float*)d_in[6];
    float* out = (float*)d_out;

    cudaFuncSetAttribute(k_conv, cudaFuncAttributeMaxDynamicSharedMemorySize,
                         CONV_SMEM_BYTES);
    cudaFuncSetAttribute(k_scatlin, cudaFuncAttributeMaxDynamicSharedMemorySize,
                         SCAT_SMEM_BYTES);

    const int zero_blocks = (int)((sizeof(GScratch) / 16 + 255) / 256);
    k_prep<<<64 + 1 + zero_blocks, 256>>>(wf, wb, ei);
    k_count<<<(N_EDGES + 255) / 256, 256>>>(ei, et);
    k_scatlin<<<SCAT_BLOCKS + LIN_BLOCKS, 256, SCAT_SMEM_BYTES>>>(et, x, lw, lb, out);
    k_conv<<<CONV_GRID, 256, CONV_SMEM_BYTES>>>(x, ei, wf, wb, out);
}